// round 15
// baseline (speedup 1.0000x reference)
#include <cuda_runtime.h>
#include <cuda_fp16.h>
#include <cstdint>

#define NB 4
#define NN 4096
#define ND 32
#define NC 256
#define BM 128
#define BN 64
#define NT (NN/BN)

// ---------------- scratch (device globals; allocation-free rule) -----------
__device__ uint32_t d_gbh[NB*NN*16];
__device__ uint32_t d_gbl[NB*NN*16];
// f^T combined bf16 fragments: uint4 (hx,hy,lx,ly) [b][key][e], e=ks*4+tq
__device__ uint4 d_fq4[NB*NN*8];
__device__ uint4 d_hf4[NB*256*4*128];

// ---------------- helpers ---------------------------------------------------
__device__ __forceinline__ uint32_t smem_u32(const void* p) {
    return (uint32_t)__cvta_generic_to_shared(p);
}
__device__ __forceinline__ void cpa16(uint32_t dst, const void* src) {
    asm volatile("cp.async.cg.shared.global [%0], [%1], 16;" :: "r"(dst), "l"(src));
}
__device__ __forceinline__ void cpa_commit() {
    asm volatile("cp.async.commit_group;" ::: "memory");
}
template<int N> __device__ __forceinline__ void cpa_wait() {
    asm volatile("cp.async.wait_group %0;" :: "n"(N) : "memory");
}
__device__ __forceinline__ void barx(int id, int cnt) {
    asm volatile("bar.sync %0, %1;" :: "r"(id), "r"(cnt) : "memory");
}
__device__ __forceinline__ float ex2(float x) {
    float r;
    asm("ex2.approx.f32 %0, %1;" : "=f"(r) : "f"(x));
    return r;
}
__device__ __forceinline__ uint32_t packbf(float lo, float hi) {
    uint32_t r;
    asm("cvt.rn.bf16x2.f32 %0, %1, %2;" : "=r"(r) : "f"(hi), "f"(lo));
    return r;
}
__device__ __forceinline__ uint32_t packf16(float lo, float hi) {
    uint32_t r;
    asm("cvt.rn.f16x2.f32 %0, %1, %2;" : "=r"(r) : "f"(hi), "f"(lo));
    return r;
}
__device__ __forceinline__ float bf_lo(uint32_t p) { return __uint_as_float(p << 16); }
__device__ __forceinline__ float bf_hi(uint32_t p) { return __uint_as_float(p & 0xffff0000u); }

__device__ __forceinline__ void mma16(float* c, const uint32_t* a, uint32_t b0, uint32_t b1) {
    asm volatile("mma.sync.aligned.m16n8k16.row.col.f32.bf16.bf16.f32 "
        "{%0,%1,%2,%3}, {%4,%5,%6,%7}, {%8,%9}, {%0,%1,%2,%3};"
        : "+f"(c[0]), "+f"(c[1]), "+f"(c[2]), "+f"(c[3])
        : "r"(a[0]), "r"(a[1]), "r"(a[2]), "r"(a[3]), "r"(b0), "r"(b1));
}
__device__ __forceinline__ void mma16h(float* c, const uint32_t* a, uint32_t b0, uint32_t b1) {
    asm volatile("mma.sync.aligned.m16n8k16.row.col.f32.f16.f16.f32 "
        "{%0,%1,%2,%3}, {%4,%5,%6,%7}, {%8,%9}, {%0,%1,%2,%3};"
        : "+f"(c[0]), "+f"(c[1]), "+f"(c[2]), "+f"(c[3])
        : "r"(a[0]), "r"(a[1]), "r"(a[2]), "r"(a[3]), "r"(b0), "r"(b1));
}
__device__ __forceinline__ unsigned long long pk2(float a, float b) {
    unsigned long long r;
    asm("mov.b64 %0, {%1, %2};" : "=l"(r) : "f"(a), "f"(b));
    return r;
}
__device__ __forceinline__ void fma2(unsigned long long& d, unsigned long long a, unsigned long long b) {
    asm("fma.rn.f32x2 %0, %1, %2, %0;" : "+l"(d) : "l"(a), "l"(b));
}
__device__ __forceinline__ void unpk2(unsigned long long v, float& a, float& b) {
    asm("mov.b64 {%0, %1}, %2;" : "=f"(a), "=f"(b) : "l"(v));
}

// ============================================================================
// Projection kernel (R14, proven): 256 CTAs x 256 threads, 64 rows each.
// Only change: f^T fragments written as combined uint4.
// ============================================================================
#define PX_STRIDE 260
#define P_XS     0
#define P_WS0    (64*PX_STRIDE)
#define P_WS1    (P_WS0 + 16384)
#define P_STG    (P_WS1 + 16384)
#define PROJ_SMEM_BYTES ((P_STG + 4224)*4)

__device__ __forceinline__ void stage_fg(uint32_t wsb, const float* Wf,
                                         const float* Wg, int t) {
    #pragma unroll
    for (int s = 0; s < 16; s++) {
        int idx = t + 256*s;
        int k = idx >> 4, c4 = idx & 15;
        if (c4 < 8) cpa16(wsb + (uint32_t)(k*64 + c4*4)*4,        Wf + k*32 + c4*4);
        else        cpa16(wsb + (uint32_t)(k*64 + 32 + (c4-8)*4)*4, Wg + k*32 + (c4-8)*4);
    }
}
__device__ __forceinline__ void stage_wh(uint32_t wsb, const float* Whp, int t) {
    #pragma unroll
    for (int s = 0; s < 16; s++) {
        int idx = t + 256*s;
        int k = idx >> 4, c4 = idx & 15;
        cpa16(wsb + (uint32_t)(k*64 + c4*4)*4, Whp + k*NC + c4*4);
    }
}

__global__ __launch_bounds__(256) void proj_kernel(
    const float* __restrict__ x,
    const float* __restrict__ Wf, const float* __restrict__ bf,
    const float* __restrict__ Wg, const float* __restrict__ bg,
    const float* __restrict__ Wh, const float* __restrict__ bh)
{
    extern __shared__ float sm[];
    float* xs  = sm + P_XS;
    float* stg = sm + P_STG;
    const uint32_t smb = smem_u32(sm);
    const int t    = threadIdx.x;
    const int R0   = blockIdx.x * 64;
    const int bb   = R0 >> 12;
    const int key0 = R0 & (NN-1);

    {
        const float4* xg = (const float4*)(x + (size_t)R0*NC);
        #pragma unroll
        for (int s = 0; s < 16; s++) {
            int idx = t + 256*s;
            int row = idx >> 6, k4 = idx & 63;
            float4 v = xg[idx];
            float* dst = &xs[row*PX_STRIDE + k4*4];
            dst[0]=v.x; dst[1]=v.y; dst[2]=v.z; dst[3]=v.w;
        }
    }

    stage_fg(smb + P_WS0*4, Wf, Wg, t);
    cpa_commit();

    const int c0 = (t & 15) * 4;
    const int r0 = (t >> 4) * 4;

    for (int ph = 0; ph < 5; ph++) {
        cpa_wait<0>();
        __syncthreads();
        if (ph < 4) {
            stage_wh(smb + (((ph+1)&1) ? P_WS1 : P_WS0)*4, Wh + ph*64, t);
            cpa_commit();
        }
        const float* ws = sm + ((ph & 1) ? P_WS1 : P_WS0);

        unsigned long long accA[4], accB[4];
        #pragma unroll
        for (int a = 0; a < 4; a++) { accA[a] = 0ull; accB[a] = 0ull; }

        #pragma unroll 2
        for (int kk = 0; kk < 128; kk++) {
            int k = kk*2;
            float4 wv0 = *(const float4*)&ws[k*64 + c0];
            float4 wv1 = *(const float4*)&ws[(k+1)*64 + c0];
            unsigned long long wA0 = pk2(wv0.x, wv0.y), wB0 = pk2(wv0.z, wv0.w);
            unsigned long long wA1 = pk2(wv1.x, wv1.y), wB1 = pk2(wv1.z, wv1.w);
            #pragma unroll
            for (int rr = 0; rr < 4; rr++) {
                float2 xv = *(const float2*)&xs[(r0+rr)*PX_STRIDE + k];
                unsigned long long xb0 = pk2(xv.x, xv.x);
                unsigned long long xb1 = pk2(xv.y, xv.y);
                fma2(accA[rr], xb0, wA0);
                fma2(accB[rr], xb0, wB0);
                fma2(accA[rr], xb1, wA1);
                fma2(accB[rr], xb1, wB1);
            }
        }

        if (ph == 0) {
            float* sfhi = stg;                // [64 keys][33]
            #pragma unroll
            for (int rr = 0; rr < 4; rr++) {
                int lrow = r0 + rr;
                int grow = R0 + lrow;
                float v[4];
                unpk2(accA[rr], v[0], v[1]);
                unpk2(accB[rr], v[2], v[3]);
                if (c0 < 32) {
                    #pragma unroll
                    for (int q = 0; q < 4; q++)
                        sfhi[lrow*33 + c0 + q] = v[q] + bf[c0 + q];
                } else {
                    float w0 = v[0] + bg[c0-32], w1 = v[1] + bg[c0-31];
                    float w2 = v[2] + bg[c0-30], w3 = v[3] + bg[c0-29];
                    uint32_t h0 = packbf(w0, w1);
                    uint32_t l0 = packbf(w0 - bf_lo(h0), w1 - bf_hi(h0));
                    uint32_t h1 = packbf(w2, w3);
                    uint32_t l1 = packbf(w2 - bf_lo(h1), w3 - bf_hi(h1));
                    int cu = (c0 - 32) >> 1;
                    d_gbh[(size_t)grow*16 + cu    ] = h0;
                    d_gbl[(size_t)grow*16 + cu    ] = l0;
                    d_gbh[(size_t)grow*16 + cu + 1] = h1;
                    d_gbl[(size_t)grow*16 + cu + 1] = l1;
                }
            }
            __syncthreads();
            // f^T combined fragment writes: 512 uint4 entries
            #pragma unroll
            for (int j = 0; j < 2; j++) {
                int idx = t + 256*j;
                int key = idx >> 3, e = idx & 7;
                int ks = e >> 2, tq2 = e & 3;
                int cb = 16*ks + 2*tq2;
                const float* fr = sfhi + key*33;
                float v0 = fr[cb], v1 = fr[cb+1], v8 = fr[cb+8], v9 = fr[cb+9];
                uint32_t hx = packbf(v0, v1);
                uint32_t hy = packbf(v8, v9);
                uint32_t lx = packbf(v0 - bf_lo(hx), v1 - bf_hi(hx));
                uint32_t ly = packbf(v8 - bf_lo(hy), v9 - bf_hi(hy));
                size_t dst = ((size_t)(bb*NN) + key0 + key)*8 + e;
                d_fq4[dst] = make_uint4(hx, hy, lx, ly);
            }
        } else {
            float* sh = stg;                  // [64 keys][65] fp32
            #pragma unroll
            for (int rr = 0; rr < 4; rr++) {
                int lrow = r0 + rr;
                float v[4];
                unpk2(accA[rr], v[0], v[1]);
                unpk2(accB[rr], v[2], v[3]);
                #pragma unroll
                for (int q = 0; q < 4; q++) {
                    int c = c0 + q;
                    sh[lrow*65 + c] = v[q] + bh[(ph-1)*64 + c];
                }
            }
            __syncthreads();
            #pragma unroll
            for (int j = 0; j < 2; j++) {
                int idx = t + 256*j;
                int K16loc = idx >> 7;
                int tqv    = (idx >> 5) & 3;
                int qv     = idx & 31;
                int k2 = K16loc*16 + 2*tqv;
                uint4 u;
                u.x = packf16(sh[k2*65+qv],        sh[(k2+1)*65+qv]);
                u.y = packf16(sh[(k2+8)*65+qv],    sh[(k2+9)*65+qv]);
                u.z = packf16(sh[k2*65+qv+32],     sh[(k2+1)*65+qv+32]);
                u.w = packf16(sh[(k2+8)*65+qv+32], sh[(k2+9)*65+qv+32]);
                size_t dst = ((size_t)(bb*256 + (key0>>4) + K16loc)*4 + tqv)*128
                           + (ph-1)*32 + qv;
                d_hf4[dst] = u;
            }
        }
    }
}

// ============================================================================
// Flash attention. fp16 PV + online row-max, pipelined (R12 structure) with:
// combined f uint4 (LDS.128), permuted P (LDS.64 A-frags), ex2-fused exp,
// register-resident row-sums (one named barrier per tile).
// ============================================================================
#define FB4_TILE   528                       // uint4: 8 e-rows x 66
#define FB4_BYTES  (FB4_TILE*16)             // 8448
#define OFF_H_B    (2*FB4_BYTES)             // 16896
#define H_STQ      130
#define H_TILE_B   (16*H_STQ*16)             // 33280
#define OFF_P_B    (OFF_H_B + 2*H_TILE_B)    // 83456
#define P_STRIDE   40
#define P_BUF_B    (128*P_STRIDE*4)          // 20480
#define OFF_SC_B   (OFF_P_B + 2*P_BUF_B)     // 124416
#define OFF_MX_B   (OFF_SC_B + 1024)
#define OFF_PS_B   (OFF_MX_B + 1024)
#define ATT_SMEM_BYTES (OFF_PS_B + 1024 + 256)

__device__ __forceinline__ void attn_load_f(uint32_t smb, int bb, int kb, int buf, int t) {
    int key = t >> 3, ep = t & 7;            // coalesced: lanes span e for one key
    const uint4* src = d_fq4 + ((size_t)(bb*NN + kb*64 + key))*8 + ep;
    cpa16(smb + (uint32_t)(buf*FB4_TILE + ep*66 + key)*16, src);
}
__device__ __forceinline__ void attn_load_h(uint32_t smb, int bb, int kb, int buf, int t) {
    #pragma unroll
    for (int s = 0; s < 4; s++) {
        int idx = t + 512*s;
        int K16loc = idx >> 9, rem = idx & 511;
        int tqv = rem >> 7, q = rem & 127;
        const uint4* src = d_hf4 + ((size_t)(bb*256 + kb*4 + K16loc)*4 + tqv)*128 + q;
        cpa16(smb + (uint32_t)(OFF_H_B + buf*H_TILE_B + ((K16loc*4+tqv)*H_STQ + q)*16), src);
    }
}

__global__ __launch_bounds__(512, 1) void attn_kernel(
    const float* __restrict__ x, float* __restrict__ out)
{
    extern __shared__ char smraw[];
    const uint32_t smb = smem_u32(smraw);
    const int t    = threadIdx.x;
    const int w    = t >> 5, lane = t & 31;
    const int g    = lane >> 2, tq = lane & 3;
    const int bb   = blockIdx.y;
    const int q0   = blockIdx.x * BM;
    const float L2E = 1.4426950408889634f;

    const int qg = w >> 1, kg = w & 1;
    const int mg = w >> 2, ng = w & 3;

    float* scbuf = (float*)(smraw + OFF_SC_B);
    float* smax  = (float*)(smraw + OFF_MX_B);
    float* psum  = (float*)(smraw + OFF_PS_B);

    uint32_t ahi[2][4], alo[2][4];
    {
        const uint32_t* gbh = d_gbh + ((size_t)(bb*NN + q0 + qg*16))*16;
        const uint32_t* gbl = d_gbl + ((size_t)(bb*NN + q0 + qg*16))*16;
        #pragma unroll
        for (int ks = 0; ks < 2; ks++) {
            int cc = 8*ks + tq;
            ahi[ks][0] = gbh[g*16 + cc];
            ahi[ks][1] = gbh[(g+8)*16 + cc];
            ahi[ks][2] = gbh[g*16 + cc + 4];
            ahi[ks][3] = gbh[(g+8)*16 + cc + 4];
            alo[ks][0] = gbl[g*16 + cc];
            alo[ks][1] = gbl[(g+8)*16 + cc];
            alo[ks][2] = gbl[g*16 + cc + 4];
            alo[ks][3] = gbl[(g+8)*16 + cc + 4];
        }
    }

    float oacc[2][8][4];
    #pragma unroll
    for (int a=0;a<2;a++)
        #pragma unroll
        for (int b2=0;b2<8;b2++)
            #pragma unroll
            for (int c=0;c<4;c++) oacc[a][b2][c]=0.f;

    const float NEGINF = __int_as_float(0xff800000);
    float mold0 = NEGINF, mold1 = NEGINF;
    float ls0 = 0.f, ls1 = 0.f;               // register row-sums
    const int row0 = qg*16 + g;

    attn_load_f(smb, bb, 0, 0, t);
    cpa_commit();

    #pragma unroll 1
    for (int kb = 0; kb < NT; kb++) {
        const int pb = kb & 1;
        if (kb + 1 < NT) attn_load_f(smb, bb, kb+1, pb^1, t);
        cpa_commit();
        attn_load_h(smb, bb, kb, pb, t);
        cpa_commit();
        cpa_wait<2>();
        __syncthreads();

        // ---- QK(kb): combined-uint4 B loads, bf16 3-term ----
        const uint4* fb4 = (const uint4*)(smraw + pb*FB4_BYTES);
        float sacc[4][4];
        #pragma unroll
        for (int nt=0;nt<4;nt++)
            #pragma unroll
            for (int c=0;c<4;c++) sacc[nt][c]=0.f;

        #pragma unroll
        for (int ks = 0; ks < 2; ks++) {
            int erow = (ks*4 + tq)*66;
            #pragma unroll
            for (int nt = 0; nt < 4; nt++) {
                int key = kg*32 + nt*8 + g;
                uint4 u = fb4[erow + key];
                mma16(sacc[nt], ahi[ks], u.z, u.w);   // ahi * flo
                mma16(sacc[nt], alo[ks], u.x, u.y);   // alo * fhi
                mma16(sacc[nt], ahi[ks], u.x, u.y);   // ahi * fhi
            }
        }

        // ---- online row max ----
        float m0 = fmaxf(fmaxf(sacc[0][0], sacc[0][1]), fmaxf(sacc[1][0], sacc[1][1]));
        m0 = fmaxf(m0, fmaxf(fmaxf(sacc[2][0], sacc[2][1]), fmaxf(sacc[3][0], sacc[3][1])));
        float m1 = fmaxf(fmaxf(sacc[0][2], sacc[0][3]), fmaxf(sacc[1][2], sacc[1][3]));
        m1 = fmaxf(m1, fmaxf(fmaxf(sacc[2][2], sacc[2][3]), fmaxf(sacc[3][2], sacc[3][3])));
        m0 = fmaxf(m0, __shfl_xor_sync(0xffffffffu, m0, 1));
        m0 = fmaxf(m0, __shfl_xor_sync(0xffffffffu, m0, 2));
        m1 = fmaxf(m1, __shfl_xor_sync(0xffffffffu, m1, 1));
        m1 = fmaxf(m1, __shfl_xor_sync(0xffffffffu, m1, 2));
        if (tq == 0) {
            smax[kg*128 + row0    ] = m0;
            smax[kg*128 + row0 + 8] = m1;
        }
        barx(1 + qg, 64);
        float mnew0 = fmaxf(mold0, fmaxf(smax[row0    ], smax[128 + row0    ]));
        float mnew1 = fmaxf(mold1, fmaxf(smax[row0 + 8], smax[128 + row0 + 8]));
        float sc0 = ex2((mold0 - mnew0) * L2E);      // 0 on first tile
        float sc1 = ex2((mold1 - mnew1) * L2E);
        mold0 = mnew0; mold1 = mnew1;
        float m2n0 = mnew0 * L2E, m2n1 = mnew1 * L2E;
        if (kg == 0 && tq == 0) {
            scbuf[pb*128 + row0    ] = sc0;
            scbuf[pb*128 + row0 + 8] = sc1;
        }

        // ---- p = ex2(s*L2E - m2), fp16 pack, permuted P store ----
        {
            uint32_t* P = (uint32_t*)(smraw + OFF_P_B + pb*P_BUF_B);
            float rs0 = 0.f, rs1 = 0.f;
            #pragma unroll
            for (int nt = 0; nt < 4; nt++) {
                float p0 = ex2(fmaf(sacc[nt][0], L2E, -m2n0));
                float p1 = ex2(fmaf(sacc[nt][1], L2E, -m2n0));
                float p2 = ex2(fmaf(sacc[nt][2], L2E, -m2n1));
                float p3 = ex2(fmaf(sacc[nt][3], L2E, -m2n1));
                uint32_t u0 = packf16(p0, p1);
                uint32_t u1 = packf16(p2, p3);
                float2 f0 = __half22float2(*(const __half2*)&u0);
                float2 f1 = __half22float2(*(const __half2*)&u1);
                rs0 += f0.x + f0.y;
                rs1 += f1.x + f1.y;
                int cp = kg*16 + nt*4 + tq;
                int pos = ((cp >> 3) << 3) + ((cp & 3) << 1) + ((cp >> 2) & 1);
                P[(row0    )*P_STRIDE + pos] = u0;
                P[(row0 + 8)*P_STRIDE + pos] = u1;
            }
            rs0 += __shfl_xor_sync(0xffffffffu, rs0, 1);
            rs0 += __shfl_xor_sync(0xffffffffu, rs0, 2);
            rs1 += __shfl_xor_sync(0xffffffffu, rs1, 1);
            rs1 += __shfl_xor_sync(0xffffffffu, rs1, 2);
            ls0 = ls0*sc0 + rs0;
            ls1 = ls1*sc1 + rs1;
        }

        // ---- PV(kb-1): LDS.64 A-frags from permuted P ----
        if (kb > 0) {
            const uint32_t* Pp = (const uint32_t*)(smraw + OFF_P_B + (pb^1)*P_BUF_B);
            const uint4*    hq = (const uint4*)(smraw + OFF_H_B + (pb^1)*H_TILE_B);
            const float*   scb = scbuf + (pb^1)*128;
            float sc[2][2];
            #pragma unroll
            for (int mt = 0; mt < 2; mt++) {
                sc[mt][0] = scb[mg*32 + mt*16 + g    ];
                sc[mt][1] = scb[mg*32 + mt*16 + g + 8];
            }
            #pragma unroll
            for (int mt = 0; mt < 2; mt++)
                #pragma unroll
                for (int nt = 0; nt < 8; nt++) {
                    oacc[mt][nt][0] *= sc[mt][0];
                    oacc[mt][nt][1] *= sc[mt][0];
                    oacc[mt][nt][2] *= sc[mt][1];
                    oacc[mt][nt][3] *= sc[mt][1];
                }
            #pragma unroll
            for (int ks = 0; ks < 4; ks++) {
                uint32_t pa[2][4];
                #pragma unroll
                for (int mt = 0; mt < 2; mt++) {
                    const uint32_t* Pr = Pp + (mg*32 + mt*16)*P_STRIDE + ks*8 + tq*2;
                    uint2 L1 = *(const uint2*)&Pr[g*P_STRIDE];
                    uint2 L2 = *(const uint2*)&Pr[(g+8)*P_STRIDE];
                    pa[mt][0] = L1.x; pa[mt][1] = L2.x;
                    pa[mt][2] = L1.y; pa[mt][3] = L2.y;
                }
                int rowb = (ks*4 + tq)*H_STQ;
                #pragma unroll
                for (int ntl = 0; ntl < 4; ntl++) {
                    uint4 u = hq[rowb + ng*32 + ntl*8 + g];
                    mma16h(oacc[0][ntl],   pa[0], u.x, u.y);
                    mma16h(oacc[1][ntl],   pa[1], u.x, u.y);
                    mma16h(oacc[0][ntl+4], pa[0], u.z, u.w);
                    mma16h(oacc[1][ntl+4], pa[1], u.z, u.w);
                }
            }
        }

        __syncthreads();
    }

    // publish register row-sums
    if (tq == 0) {
        psum[kg*128 + row0    ] = ls0;
        psum[kg*128 + row0 + 8] = ls1;
    }
    cpa_wait<0>();
    __syncthreads();

    // ---- final PV(NT-1) ----
    {
        const int pb = (NT-1) & 1;
        const uint32_t* Pp = (const uint32_t*)(smraw + OFF_P_B + pb*P_BUF_B);
        const uint4*    hq = (const uint4*)(smraw + OFF_H_B + pb*H_TILE_B);
        const float*   scb = scbuf + pb*128;
        float sc[2][2];
        #pragma unroll
        for (int mt = 0; mt < 2; mt++) {
            sc[mt][0] = scb[mg*32 + mt*16 + g    ];
            sc[mt][1] = scb[mg*32 + mt*16 + g + 8];
        }
        #pragma unroll
        for (int mt = 0; mt < 2; mt++)
            #pragma unroll
            for (int nt = 0; nt < 8; nt++) {
                oacc[mt][nt][0] *= sc[mt][0];
                oacc[mt][nt][1] *= sc[mt][0];
                oacc[mt][nt][2] *= sc[mt][1];
                oacc[mt][nt][3] *= sc[mt][1];
            }
        #pragma unroll
        for (int ks = 0; ks < 4; ks++) {
            uint32_t pa[2][4];
            #pragma unroll
            for (int mt = 0; mt < 2; mt++) {
                const uint32_t* Pr = Pp + (mg*32 + mt*16)*P_STRIDE + ks*8 + tq*2;
                uint2 L1 = *(const uint2*)&Pr[g*P_STRIDE];
                uint2 L2 = *(const uint2*)&Pr[(g+8)*P_STRIDE];
                pa[mt][0] = L1.x; pa[mt][1] = L2.x;
                pa[mt][2] = L1.y; pa[mt][3] = L2.y;
            }
            int rowb = (ks*4 + tq)*H_STQ;
            #pragma unroll
            for (int ntl = 0; ntl < 4; ntl++) {
                uint4 u = hq[rowb + ng*32 + ntl*8 + g];
                mma16h(oacc[0][ntl],   pa[0], u.x, u.y);
                mma16h(oacc[1][ntl],   pa[1], u.x, u.y);
                mma16h(oacc[0][ntl+4], pa[0], u.z, u.w);
                mma16h(oacc[1][ntl+4], pa[1], u.z, u.w);
            }
        }
    }

    // ---- epilogue: out = x + O / l ----
    #pragma unroll
    for (int mt = 0; mt < 2; mt++) {
        int r0 = mg*32 + mt*16 + g;
        float inv0 = 1.0f / (psum[r0    ] + psum[128 + r0    ]);
        float inv1 = 1.0f / (psum[r0 + 8] + psum[128 + r0 + 8]);
        #pragma unroll
        for (int nt = 0; nt < 8; nt++) {
            int col = ng*64 + nt*8 + 2*tq;
            size_t base0 = ((size_t)(bb*NN + q0 + r0))*NC + col;
            size_t base1 = base0 + (size_t)8*NC;
            float2 xv0 = *(const float2*)(x + base0);
            float2 xv1 = *(const float2*)(x + base1);
            float2 o0, o1;
            o0.x = xv0.x + oacc[mt][nt][0]*inv0;
            o0.y = xv0.y + oacc[mt][nt][1]*inv0;
            o1.x = xv1.x + oacc[mt][nt][2]*inv1;
            o1.y = xv1.y + oacc[mt][nt][3]*inv1;
            *(float2*)(out + base0) = o0;
            *(float2*)(out + base1) = o1;
        }
    }
}

extern "C" void kernel_launch(void* const* d_in, const int* in_sizes, int n_in,
                              void* d_out, int out_size) {
    (void)in_sizes; (void)n_in; (void)out_size;
    const float* x  = (const float*)d_in[0];
    const float* Wf = (const float*)d_in[1];
    const float* bf = (const float*)d_in[2];
    const float* Wg = (const float*)d_in[3];
    const float* bg = (const float*)d_in[4];
    const float* Wh = (const float*)d_in[5];
    const float* bh = (const float*)d_in[6];
    float* out = (float*)d_out;

    cudaFuncSetAttribute(proj_kernel, cudaFuncAttributeMaxDynamicSharedMemorySize,
                         PROJ_SMEM_BYTES);
    cudaFuncSetAttribute(attn_kernel, cudaFuncAttributeMaxDynamicSharedMemorySize,
                         ATT_SMEM_BYTES);

    proj_kernel<<<(NB*NN)/64, 256, PROJ_SMEM_BYTES>>>(x, Wf, bf, Wg, bg, Wh, bh);

    dim3 grid(NN/BM, NB);
    attn_kernel<<<grid, 512, ATT_SMEM_BYTES>>>(x, out);
}

// round 16
// speedup vs baseline: 1.1639x; 1.1639x over previous
#include <cuda_runtime.h>
#include <cuda_fp16.h>
#include <cstdint>

#define NB 4
#define NN 4096
#define ND 32
#define NC 256
#define BM 128
#define BN 64
#define NT (NN/BN)

// ---------------- scratch (device globals; allocation-free rule) -----------
__device__ uint32_t d_gbh[NB*NN*16];
__device__ uint32_t d_gbl[NB*NN*16];
__device__ uint2 d_fqh[NB*NN*8];
__device__ uint2 d_fql[NB*NN*8];
__device__ uint4 d_hf4[NB*256*4*128];

// ---------------- helpers ---------------------------------------------------
__device__ __forceinline__ uint32_t smem_u32(const void* p) {
    return (uint32_t)__cvta_generic_to_shared(p);
}
__device__ __forceinline__ void cpa16(uint32_t dst, const void* src) {
    asm volatile("cp.async.cg.shared.global [%0], [%1], 16;" :: "r"(dst), "l"(src));
}
__device__ __forceinline__ void cpa_commit() {
    asm volatile("cp.async.commit_group;" ::: "memory");
}
template<int N> __device__ __forceinline__ void cpa_wait() {
    asm volatile("cp.async.wait_group %0;" :: "n"(N) : "memory");
}
__device__ __forceinline__ void barx(int id, int cnt) {
    asm volatile("bar.sync %0, %1;" :: "r"(id), "r"(cnt) : "memory");
}
__device__ __forceinline__ float ex2(float x) {
    float r;
    asm("ex2.approx.f32 %0, %1;" : "=f"(r) : "f"(x));
    return r;
}
__device__ __forceinline__ uint32_t packbf(float lo, float hi) {
    uint32_t r;
    asm("cvt.rn.bf16x2.f32 %0, %1, %2;" : "=r"(r) : "f"(hi), "f"(lo));
    return r;
}
__device__ __forceinline__ uint32_t packf16(float lo, float hi) {
    uint32_t r;
    asm("cvt.rn.f16x2.f32 %0, %1, %2;" : "=r"(r) : "f"(hi), "f"(lo));
    return r;
}
__device__ __forceinline__ float bf_lo(uint32_t p) { return __uint_as_float(p << 16); }
__device__ __forceinline__ float bf_hi(uint32_t p) { return __uint_as_float(p & 0xffff0000u); }

__device__ __forceinline__ void mma16(float* c, const uint32_t* a, uint32_t b0, uint32_t b1) {
    asm volatile("mma.sync.aligned.m16n8k16.row.col.f32.bf16.bf16.f32 "
        "{%0,%1,%2,%3}, {%4,%5,%6,%7}, {%8,%9}, {%0,%1,%2,%3};"
        : "+f"(c[0]), "+f"(c[1]), "+f"(c[2]), "+f"(c[3])
        : "r"(a[0]), "r"(a[1]), "r"(a[2]), "r"(a[3]), "r"(b0), "r"(b1));
}
__device__ __forceinline__ void mma16h(float* c, const uint32_t* a, uint32_t b0, uint32_t b1) {
    asm volatile("mma.sync.aligned.m16n8k16.row.col.f32.f16.f16.f32 "
        "{%0,%1,%2,%3}, {%4,%5,%6,%7}, {%8,%9}, {%0,%1,%2,%3};"
        : "+f"(c[0]), "+f"(c[1]), "+f"(c[2]), "+f"(c[3])
        : "r"(a[0]), "r"(a[1]), "r"(a[2]), "r"(a[3]), "r"(b0), "r"(b1));
}
__device__ __forceinline__ unsigned long long pk2(float a, float b) {
    unsigned long long r;
    asm("mov.b64 %0, {%1, %2};" : "=l"(r) : "f"(a), "f"(b));
    return r;
}
__device__ __forceinline__ void fma2(unsigned long long& d, unsigned long long a, unsigned long long b) {
    asm("fma.rn.f32x2 %0, %1, %2, %0;" : "+l"(d) : "l"(a), "l"(b));
}
__device__ __forceinline__ void unpk2(unsigned long long v, float& a, float& b) {
    asm("mov.b64 {%0, %1}, %2;" : "=f"(a), "=f"(b) : "l"(v));
}

// ============================================================================
// Projection kernel (R14, proven): 256 CTAs x 256 threads, 64 rows each.
// ============================================================================
#define PX_STRIDE 260
#define P_XS     0
#define P_WS0    (64*PX_STRIDE)
#define P_WS1    (P_WS0 + 16384)
#define P_STG    (P_WS1 + 16384)
#define PROJ_SMEM_BYTES ((P_STG + 4224)*4)

__device__ __forceinline__ void stage_fg(uint32_t wsb, const float* Wf,
                                         const float* Wg, int t) {
    #pragma unroll
    for (int s = 0; s < 16; s++) {
        int idx = t + 256*s;
        int k = idx >> 4, c4 = idx & 15;
        if (c4 < 8) cpa16(wsb + (uint32_t)(k*64 + c4*4)*4,        Wf + k*32 + c4*4);
        else        cpa16(wsb + (uint32_t)(k*64 + 32 + (c4-8)*4)*4, Wg + k*32 + (c4-8)*4);
    }
}
__device__ __forceinline__ void stage_wh(uint32_t wsb, const float* Whp, int t) {
    #pragma unroll
    for (int s = 0; s < 16; s++) {
        int idx = t + 256*s;
        int k = idx >> 4, c4 = idx & 15;
        cpa16(wsb + (uint32_t)(k*64 + c4*4)*4, Whp + k*NC + c4*4);
    }
}

__global__ __launch_bounds__(256) void proj_kernel(
    const float* __restrict__ x,
    const float* __restrict__ Wf, const float* __restrict__ bf,
    const float* __restrict__ Wg, const float* __restrict__ bg,
    const float* __restrict__ Wh, const float* __restrict__ bh)
{
    extern __shared__ float sm[];
    float* xs  = sm + P_XS;
    float* stg = sm + P_STG;
    const uint32_t smb = smem_u32(sm);
    const int t    = threadIdx.x;
    const int R0   = blockIdx.x * 64;
    const int bb   = R0 >> 12;
    const int key0 = R0 & (NN-1);

    {
        const float4* xg = (const float4*)(x + (size_t)R0*NC);
        #pragma unroll
        for (int s = 0; s < 16; s++) {
            int idx = t + 256*s;
            int row = idx >> 6, k4 = idx & 63;
            float4 v = xg[idx];
            float* dst = &xs[row*PX_STRIDE + k4*4];
            dst[0]=v.x; dst[1]=v.y; dst[2]=v.z; dst[3]=v.w;
        }
    }

    stage_fg(smb + P_WS0*4, Wf, Wg, t);
    cpa_commit();

    const int c0 = (t & 15) * 4;
    const int r0 = (t >> 4) * 4;

    for (int ph = 0; ph < 5; ph++) {
        cpa_wait<0>();
        __syncthreads();
        if (ph < 4) {
            stage_wh(smb + (((ph+1)&1) ? P_WS1 : P_WS0)*4, Wh + ph*64, t);
            cpa_commit();
        }
        const float* ws = sm + ((ph & 1) ? P_WS1 : P_WS0);

        unsigned long long accA[4], accB[4];
        #pragma unroll
        for (int a = 0; a < 4; a++) { accA[a] = 0ull; accB[a] = 0ull; }

        #pragma unroll 2
        for (int kk = 0; kk < 128; kk++) {
            int k = kk*2;
            float4 wv0 = *(const float4*)&ws[k*64 + c0];
            float4 wv1 = *(const float4*)&ws[(k+1)*64 + c0];
            unsigned long long wA0 = pk2(wv0.x, wv0.y), wB0 = pk2(wv0.z, wv0.w);
            unsigned long long wA1 = pk2(wv1.x, wv1.y), wB1 = pk2(wv1.z, wv1.w);
            #pragma unroll
            for (int rr = 0; rr < 4; rr++) {
                float2 xv = *(const float2*)&xs[(r0+rr)*PX_STRIDE + k];
                unsigned long long xb0 = pk2(xv.x, xv.x);
                unsigned long long xb1 = pk2(xv.y, xv.y);
                fma2(accA[rr], xb0, wA0);
                fma2(accB[rr], xb0, wB0);
                fma2(accA[rr], xb1, wA1);
                fma2(accB[rr], xb1, wB1);
            }
        }

        if (ph == 0) {
            float* sfhi = stg;                // [64 keys][33]
            #pragma unroll
            for (int rr = 0; rr < 4; rr++) {
                int lrow = r0 + rr;
                int grow = R0 + lrow;
                float v[4];
                unpk2(accA[rr], v[0], v[1]);
                unpk2(accB[rr], v[2], v[3]);
                if (c0 < 32) {
                    #pragma unroll
                    for (int q = 0; q < 4; q++)
                        sfhi[lrow*33 + c0 + q] = v[q] + bf[c0 + q];
                } else {
                    float w0 = v[0] + bg[c0-32], w1 = v[1] + bg[c0-31];
                    float w2 = v[2] + bg[c0-30], w3 = v[3] + bg[c0-29];
                    uint32_t h0 = packbf(w0, w1);
                    uint32_t l0 = packbf(w0 - bf_lo(h0), w1 - bf_hi(h0));
                    uint32_t h1 = packbf(w2, w3);
                    uint32_t l1 = packbf(w2 - bf_lo(h1), w3 - bf_hi(h1));
                    int cu = (c0 - 32) >> 1;
                    d_gbh[(size_t)grow*16 + cu    ] = h0;
                    d_gbl[(size_t)grow*16 + cu    ] = l0;
                    d_gbh[(size_t)grow*16 + cu + 1] = h1;
                    d_gbl[(size_t)grow*16 + cu + 1] = l1;
                }
            }
            __syncthreads();
            #pragma unroll
            for (int j = 0; j < 2; j++) {
                int idx = t + 256*j;
                int key = idx >> 3, e = idx & 7;
                int ks = e >> 2, tq2 = e & 3;
                int cb = 16*ks + 2*tq2;
                const float* fr = sfhi + key*33;
                float v0 = fr[cb], v1 = fr[cb+1], v8 = fr[cb+8], v9 = fr[cb+9];
                uint32_t hx = packbf(v0, v1);
                uint32_t hy = packbf(v8, v9);
                uint32_t lx = packbf(v0 - bf_lo(hx), v1 - bf_hi(hx));
                uint32_t ly = packbf(v8 - bf_lo(hy), v9 - bf_hi(hy));
                size_t dst = ((size_t)(bb*NN) + key0 + key)*8 + e;
                d_fqh[dst] = make_uint2(hx, hy);
                d_fql[dst] = make_uint2(lx, ly);
            }
        } else {
            float* sh = stg;                  // [64 keys][65] fp32
            #pragma unroll
            for (int rr = 0; rr < 4; rr++) {
                int lrow = r0 + rr;
                float v[4];
                unpk2(accA[rr], v[0], v[1]);
                unpk2(accB[rr], v[2], v[3]);
                #pragma unroll
                for (int q = 0; q < 4; q++) {
                    int c = c0 + q;
                    sh[lrow*65 + c] = v[q] + bh[(ph-1)*64 + c];
                }
            }
            __syncthreads();
            #pragma unroll
            for (int j = 0; j < 2; j++) {
                int idx = t + 256*j;
                int K16loc = idx >> 7;
                int tqv    = (idx >> 5) & 3;
                int qv     = idx & 31;
                int k2 = K16loc*16 + 2*tqv;
                uint4 u;
                u.x = packf16(sh[k2*65+qv],        sh[(k2+1)*65+qv]);
                u.y = packf16(sh[(k2+8)*65+qv],    sh[(k2+9)*65+qv]);
                u.z = packf16(sh[k2*65+qv+32],     sh[(k2+1)*65+qv+32]);
                u.w = packf16(sh[(k2+8)*65+qv+32], sh[(k2+9)*65+qv+32]);
                size_t dst = ((size_t)(bb*256 + (key0>>4) + K16loc)*4 + tqv)*128
                           + (ph-1)*32 + qv;
                d_hf4[dst] = u;
            }
        }
    }
}

// ============================================================================
// Flash attention (R14 layout) + ex2-fused exp + register row-sums.
// fp16 PV + online row-max, QK/PV software-pipelined. Grid (32,4), 512 thr.
// ============================================================================
#define FB_BYTES   6144
#define OFF_H_B    (4*FB_BYTES)
#define H_STQ      130
#define H_TILE_B   (16*H_STQ*16)
#define OFF_P_B    (OFF_H_B + 2*H_TILE_B)
#define P_STRIDE   36
#define P_BUF_B    (128*P_STRIDE*4)
#define OFF_SC_B   (OFF_P_B + 2*P_BUF_B)
#define OFF_MX_B   (OFF_SC_B + 1024)
#define OFF_PS_B   (OFF_MX_B + 1024)
#define ATT_SMEM_BYTES (OFF_PS_B + 1024 + 256)

__device__ __forceinline__ void attn_load_f(uint32_t smb, int bb, int kb, int buf, int t) {
    int arr = t >> 8, rem = t & 255;
    int key = rem >> 2, ep = rem & 3;
    const uint2* src = (arr ? d_fql : d_fqh)
                     + ((size_t)(bb*NN + kb*64 + key))*8 + ep*2;
    cpa16(smb + (uint32_t)((buf*2+arr)*FB_BYTES + key*96 + ep*16), src);
}
__device__ __forceinline__ void attn_load_h(uint32_t smb, int bb, int kb, int buf, int t) {
    #pragma unroll
    for (int s = 0; s < 4; s++) {
        int idx = t + 512*s;
        int K16loc = idx >> 9, rem = idx & 511;
        int tqv = rem >> 7, q = rem & 127;
        const uint4* src = d_hf4 + ((size_t)(bb*256 + kb*4 + K16loc)*4 + tqv)*128 + q;
        cpa16(smb + (uint32_t)(OFF_H_B + buf*H_TILE_B + ((K16loc*4+tqv)*H_STQ + q)*16), src);
    }
}

__global__ __launch_bounds__(512, 1) void attn_kernel(
    const float* __restrict__ x, float* __restrict__ out)
{
    extern __shared__ char smraw[];
    const uint32_t smb = smem_u32(smraw);
    const int t    = threadIdx.x;
    const int w    = t >> 5, lane = t & 31;
    const int g    = lane >> 2, tq = lane & 3;
    const int bb   = blockIdx.y;
    const int q0   = blockIdx.x * BM;
    const float L2E = 1.4426950408889634f;

    const int qg = w >> 1, kg = w & 1;
    const int mg = w >> 2, ng = w & 3;

    float* scbuf = (float*)(smraw + OFF_SC_B);
    float* smax  = (float*)(smraw + OFF_MX_B);
    float* psum  = (float*)(smraw + OFF_PS_B);

    uint32_t ahi[2][4], alo[2][4];
    {
        const uint32_t* gbh = d_gbh + ((size_t)(bb*NN + q0 + qg*16))*16;
        const uint32_t* gbl = d_gbl + ((size_t)(bb*NN + q0 + qg*16))*16;
        #pragma unroll
        for (int ks = 0; ks < 2; ks++) {
            int cc = 8*ks + tq;
            ahi[ks][0] = gbh[g*16 + cc];
            ahi[ks][1] = gbh[(g+8)*16 + cc];
            ahi[ks][2] = gbh[g*16 + cc + 4];
            ahi[ks][3] = gbh[(g+8)*16 + cc + 4];
            alo[ks][0] = gbl[g*16 + cc];
            alo[ks][1] = gbl[(g+8)*16 + cc];
            alo[ks][2] = gbl[g*16 + cc + 4];
            alo[ks][3] = gbl[(g+8)*16 + cc + 4];
        }
    }

    float oacc[2][8][4];
    #pragma unroll
    for (int a=0;a<2;a++)
        #pragma unroll
        for (int b2=0;b2<8;b2++)
            #pragma unroll
            for (int c=0;c<4;c++) oacc[a][b2][c]=0.f;

    const float NEGINF = __int_as_float(0xff800000);
    float mold0 = NEGINF, mold1 = NEGINF;
    float ls0 = 0.f, ls1 = 0.f;               // register row-sums
    const int row0 = qg*16 + g;

    attn_load_f(smb, bb, 0, 0, t);
    cpa_commit();

    #pragma unroll 1
    for (int kb = 0; kb < NT; kb++) {
        const int pb = kb & 1;
        if (kb + 1 < NT) attn_load_f(smb, bb, kb+1, pb^1, t);
        cpa_commit();
        attn_load_h(smb, bb, kb, pb, t);
        cpa_commit();
        cpa_wait<2>();
        __syncthreads();

        const uint2* fbh = (const uint2*)(smraw + (pb*2+0)*FB_BYTES);
        const uint2* fbl = (const uint2*)(smraw + (pb*2+1)*FB_BYTES);
        float sacc[4][4];
        #pragma unroll
        for (int nt=0;nt<4;nt++)
            #pragma unroll
            for (int c=0;c<4;c++) sacc[nt][c]=0.f;

        #pragma unroll
        for (int ks = 0; ks < 2; ks++) {
            #pragma unroll
            for (int nt = 0; nt < 4; nt++) {
                int key = kg*32 + nt*8 + g;
                uint2 qh = fbh[key*12 + ks*4 + tq];
                uint2 ql = fbl[key*12 + ks*4 + tq];
                mma16(sacc[nt], ahi[ks], ql.x, ql.y);
                mma16(sacc[nt], alo[ks], qh.x, qh.y);
                mma16(sacc[nt], ahi[ks], qh.x, qh.y);
            }
        }

        // ---- online row max ----
        float m0 = fmaxf(fmaxf(sacc[0][0], sacc[0][1]), fmaxf(sacc[1][0], sacc[1][1]));
        m0 = fmaxf(m0, fmaxf(fmaxf(sacc[2][0], sacc[2][1]), fmaxf(sacc[3][0], sacc[3][1])));
        float m1 = fmaxf(fmaxf(sacc[0][2], sacc[0][3]), fmaxf(sacc[1][2], sacc[1][3]));
        m1 = fmaxf(m1, fmaxf(fmaxf(sacc[2][2], sacc[2][3]), fmaxf(sacc[3][2], sacc[3][3])));
        m0 = fmaxf(m0, __shfl_xor_sync(0xffffffffu, m0, 1));
        m0 = fmaxf(m0, __shfl_xor_sync(0xffffffffu, m0, 2));
        m1 = fmaxf(m1, __shfl_xor_sync(0xffffffffu, m1, 1));
        m1 = fmaxf(m1, __shfl_xor_sync(0xffffffffu, m1, 2));
        if (tq == 0) {
            smax[kg*128 + row0    ] = m0;
            smax[kg*128 + row0 + 8] = m1;
        }
        barx(1 + qg, 64);
        float mnew0 = fmaxf(mold0, fmaxf(smax[row0    ], smax[128 + row0    ]));
        float mnew1 = fmaxf(mold1, fmaxf(smax[row0 + 8], smax[128 + row0 + 8]));
        float sc0 = ex2((mold0 - mnew0) * L2E);      // 0 on first tile
        float sc1 = ex2((mold1 - mnew1) * L2E);
        mold0 = mnew0; mold1 = mnew1;
        float m2n0 = mnew0 * L2E, m2n1 = mnew1 * L2E;
        if (kg == 0 && tq == 0) {
            scbuf[pb*128 + row0    ] = sc0;
            scbuf[pb*128 + row0 + 8] = sc1;
        }

        // ---- p = ex2(s*L2E - m2), fp16 pack, P store, register row-sums ----
        {
            uint32_t* P = (uint32_t*)(smraw + OFF_P_B + pb*P_BUF_B);
            float rs0 = 0.f, rs1 = 0.f;
            #pragma unroll
            for (int nt = 0; nt < 4; nt++) {
                float p0 = ex2(fmaf(sacc[nt][0], L2E, -m2n0));
                float p1 = ex2(fmaf(sacc[nt][1], L2E, -m2n0));
                float p2 = ex2(fmaf(sacc[nt][2], L2E, -m2n1));
                float p3 = ex2(fmaf(sacc[nt][3], L2E, -m2n1));
                uint32_t u0 = packf16(p0, p1);
                uint32_t u1 = packf16(p2, p3);
                float2 f0 = __half22float2(*(const __half2*)&u0);
                float2 f1 = __half22float2(*(const __half2*)&u1);
                rs0 += f0.x + f0.y;
                rs1 += f1.x + f1.y;
                int cp = kg*16 + nt*4 + tq;
                P[(row0    )*P_STRIDE + cp] = u0;
                P[(row0 + 8)*P_STRIDE + cp] = u1;
            }
            rs0 += __shfl_xor_sync(0xffffffffu, rs0, 1);
            rs0 += __shfl_xor_sync(0xffffffffu, rs0, 2);
            rs1 += __shfl_xor_sync(0xffffffffu, rs1, 1);
            rs1 += __shfl_xor_sync(0xffffffffu, rs1, 2);
            ls0 = ls0*sc0 + rs0;
            ls1 = ls1*sc1 + rs1;
        }

        // ---- PV(kb-1) ----
        if (kb > 0) {
            const uint32_t* Pp = (const uint32_t*)(smraw + OFF_P_B + (pb^1)*P_BUF_B);
            const uint4*    hq = (const uint4*)(smraw + OFF_H_B + (pb^1)*H_TILE_B);
            const float*   scb = scbuf + (pb^1)*128;
            float sc[2][2];
            #pragma unroll
            for (int mt = 0; mt < 2; mt++) {
                sc[mt][0] = scb[mg*32 + mt*16 + g    ];
                sc[mt][1] = scb[mg*32 + mt*16 + g + 8];
            }
            #pragma unroll
            for (int mt = 0; mt < 2; mt++)
                #pragma unroll
                for (int nt = 0; nt < 8; nt++) {
                    oacc[mt][nt][0] *= sc[mt][0];
                    oacc[mt][nt][1] *= sc[mt][0];
                    oacc[mt][nt][2] *= sc[mt][1];
                    oacc[mt][nt][3] *= sc[mt][1];
                }
            #pragma unroll
            for (int ks = 0; ks < 4; ks++) {
                uint32_t pa[2][4];
                #pragma unroll
                for (int mt = 0; mt < 2; mt++) {
                    int r = mg*32 + mt*16;
                    pa[mt][0] = Pp[(r+g  )*P_STRIDE + ks*8 + tq    ];
                    pa[mt][1] = Pp[(r+g+8)*P_STRIDE + ks*8 + tq    ];
                    pa[mt][2] = Pp[(r+g  )*P_STRIDE + ks*8 + tq + 4];
                    pa[mt][3] = Pp[(r+g+8)*P_STRIDE + ks*8 + tq + 4];
                }
                int rowb = (ks*4 + tq)*H_STQ;
                #pragma unroll
                for (int ntl = 0; ntl < 4; ntl++) {
                    uint4 u = hq[rowb + ng*32 + ntl*8 + g];
                    mma16h(oacc[0][ntl],   pa[0], u.x, u.y);
                    mma16h(oacc[1][ntl],   pa[1], u.x, u.y);
                    mma16h(oacc[0][ntl+4], pa[0], u.z, u.w);
                    mma16h(oacc[1][ntl+4], pa[1], u.z, u.w);
                }
            }
        }

        __syncthreads();
    }

    // publish register row-sums
    if (tq == 0) {
        psum[kg*128 + row0    ] = ls0;
        psum[kg*128 + row0 + 8] = ls1;
    }
    cpa_wait<0>();
    __syncthreads();

    // ---- final PV(NT-1) ----
    {
        const int pb = (NT-1) & 1;
        const uint32_t* Pp = (const uint32_t*)(smraw + OFF_P_B + pb*P_BUF_B);
        const uint4*    hq = (const uint4*)(smraw + OFF_H_B + pb*H_TILE_B);
        const float*   scb = scbuf + pb*128;
        float sc[2][2];
        #pragma unroll
        for (int mt = 0; mt < 2; mt++) {
            sc[mt][0] = scb[mg*32 + mt*16 + g    ];
            sc[mt][1] = scb[mg*32 + mt*16 + g + 8];
        }
        #pragma unroll
        for (int mt = 0; mt < 2; mt++)
            #pragma unroll
            for (int nt = 0; nt < 8; nt++) {
                oacc[mt][nt][0] *= sc[mt][0];
                oacc[mt][nt][1] *= sc[mt][0];
                oacc[mt][nt][2] *= sc[mt][1];
                oacc[mt][nt][3] *= sc[mt][1];
            }
        #pragma unroll
        for (int ks = 0; ks < 4; ks++) {
            uint32_t pa[2][4];
            #pragma unroll
            for (int mt = 0; mt < 2; mt++) {
                int r = mg*32 + mt*16;
                pa[mt][0] = Pp[(r+g  )*P_STRIDE + ks*8 + tq    ];
                pa[mt][1] = Pp[(r+g+8)*P_STRIDE + ks*8 + tq    ];
                pa[mt][2] = Pp[(r+g  )*P_STRIDE + ks*8 + tq + 4];
                pa[mt][3] = Pp[(r+g+8)*P_STRIDE + ks*8 + tq + 4];
            }
            int rowb = (ks*4 + tq)*H_STQ;
            #pragma unroll
            for (int ntl = 0; ntl < 4; ntl++) {
                uint4 u = hq[rowb + ng*32 + ntl*8 + g];
                mma16h(oacc[0][ntl],   pa[0], u.x, u.y);
                mma16h(oacc[1][ntl],   pa[1], u.x, u.y);
                mma16h(oacc[0][ntl+4], pa[0], u.z, u.w);
                mma16h(oacc[1][ntl+4], pa[1], u.z, u.w);
            }
        }
    }

    // ---- epilogue: out = x + O / l ----
    #pragma unroll
    for (int mt = 0; mt < 2; mt++) {
        int r0 = mg*32 + mt*16 + g;
        float inv0 = 1.0f / (psum[r0    ] + psum[128 + r0    ]);
        float inv1 = 1.0f / (psum[r0 + 8] + psum[128 + r0 + 8]);
        #pragma unroll
        for (int nt = 0; nt < 8; nt++) {
            int col = ng*64 + nt*8 + 2*tq;
            size_t base0 = ((size_t)(bb*NN + q0 + r0))*NC + col;
            size_t base1 = base0 + (size_t)8*NC;
            float2 xv0 = *(const float2*)(x + base0);
            float2 xv1 = *(const float2*)(x + base1);
            float2 o0, o1;
            o0.x = xv0.x + oacc[mt][nt][0]*inv0;
            o0.y = xv0.y + oacc[mt][nt][1]*inv0;
            o1.x = xv1.x + oacc[mt][nt][2]*inv1;
            o1.y = xv1.y + oacc[mt][nt][3]*inv1;
            *(float2*)(out + base0) = o0;
            *(float2*)(out + base1) = o1;
        }
    }
}

extern "C" void kernel_launch(void* const* d_in, const int* in_sizes, int n_in,
                              void* d_out, int out_size) {
    (void)in_sizes; (void)n_in; (void)out_size;
    const float* x  = (const float*)d_in[0];
    const float* Wf = (const float*)d_in[1];
    const float* bf = (const float*)d_in[2];
    const float* Wg = (const float*)d_in[3];
    const float* bg = (const float*)d_in[4];
    const float* Wh = (const float*)d_in[5];
    const float* bh = (const float*)d_in[6];
    float* out = (float*)d_out;

    cudaFuncSetAttribute(proj_kernel, cudaFuncAttributeMaxDynamicSharedMemorySize,
                         PROJ_SMEM_BYTES);
    cudaFuncSetAttribute(attn_kernel, cudaFuncAttributeMaxDynamicSharedMemorySize,
                         ATT_SMEM_BYTES);

    proj_kernel<<<(NB*NN)/64, 256, PROJ_SMEM_BYTES>>>(x, Wf, bf, Wg, bg, Wh, bh);

    dim3 grid(NN/BM, NB);
    attn_kernel<<<grid, 512, ATT_SMEM_BYTES>>>(x, out);
}

// round 17
// speedup vs baseline: 1.2718x; 1.0927x over previous
#include <cuda_runtime.h>
#include <cuda_fp16.h>
#include <cstdint>

#define NB 4
#define NN 4096
#define ND 32
#define NC 256
#define BM 128
#define BN 64
#define NT (NN/BN)

// ---------------- scratch (device globals; allocation-free rule) -----------
__device__ uint32_t d_gbh[NB*NN*16];
__device__ uint32_t d_gbl[NB*NN*16];
__device__ uint2 d_fqh[NB*NN*8];
__device__ uint2 d_fql[NB*NN*8];
__device__ uint4 d_hf4[NB*256*4*128];

// ---------------- helpers ---------------------------------------------------
__device__ __forceinline__ uint32_t smem_u32(const void* p) {
    return (uint32_t)__cvta_generic_to_shared(p);
}
__device__ __forceinline__ void cpa16(uint32_t dst, const void* src) {
    asm volatile("cp.async.cg.shared.global [%0], [%1], 16;" :: "r"(dst), "l"(src));
}
__device__ __forceinline__ void cpa_commit() {
    asm volatile("cp.async.commit_group;" ::: "memory");
}
template<int N> __device__ __forceinline__ void cpa_wait() {
    asm volatile("cp.async.wait_group %0;" :: "n"(N) : "memory");
}
__device__ __forceinline__ void barx(int id, int cnt) {
    asm volatile("bar.sync %0, %1;" :: "r"(id), "r"(cnt) : "memory");
}
__device__ __forceinline__ float ex2(float x) {
    float r;
    asm("ex2.approx.f32 %0, %1;" : "=f"(r) : "f"(x));
    return r;
}
__device__ __forceinline__ uint32_t packbf(float lo, float hi) {
    uint32_t r;
    asm("cvt.rn.bf16x2.f32 %0, %1, %2;" : "=r"(r) : "f"(hi), "f"(lo));
    return r;
}
__device__ __forceinline__ uint32_t packf16(float lo, float hi) {
    uint32_t r;
    asm("cvt.rn.f16x2.f32 %0, %1, %2;" : "=r"(r) : "f"(hi), "f"(lo));
    return r;
}
__device__ __forceinline__ float bf_lo(uint32_t p) { return __uint_as_float(p << 16); }
__device__ __forceinline__ float bf_hi(uint32_t p) { return __uint_as_float(p & 0xffff0000u); }

__device__ __forceinline__ void mma16(float* c, const uint32_t* a, uint32_t b0, uint32_t b1) {
    asm volatile("mma.sync.aligned.m16n8k16.row.col.f32.bf16.bf16.f32 "
        "{%0,%1,%2,%3}, {%4,%5,%6,%7}, {%8,%9}, {%0,%1,%2,%3};"
        : "+f"(c[0]), "+f"(c[1]), "+f"(c[2]), "+f"(c[3])
        : "r"(a[0]), "r"(a[1]), "r"(a[2]), "r"(a[3]), "r"(b0), "r"(b1));
}
__device__ __forceinline__ void mma16h(float* c, const uint32_t* a, uint32_t b0, uint32_t b1) {
    asm volatile("mma.sync.aligned.m16n8k16.row.col.f32.f16.f16.f32 "
        "{%0,%1,%2,%3}, {%4,%5,%6,%7}, {%8,%9}, {%0,%1,%2,%3};"
        : "+f"(c[0]), "+f"(c[1]), "+f"(c[2]), "+f"(c[3])
        : "r"(a[0]), "r"(a[1]), "r"(a[2]), "r"(a[3]), "r"(b0), "r"(b1));
}
__device__ __forceinline__ unsigned long long pk2(float a, float b) {
    unsigned long long r;
    asm("mov.b64 %0, {%1, %2};" : "=l"(r) : "f"(a), "f"(b));
    return r;
}
__device__ __forceinline__ void fma2(unsigned long long& d, unsigned long long a, unsigned long long b) {
    asm("fma.rn.f32x2 %0, %1, %2, %0;" : "+l"(d) : "l"(a), "l"(b));
}
__device__ __forceinline__ void unpk2(unsigned long long v, float& a, float& b) {
    asm("mov.b64 {%0, %1}, %2;" : "=f"(a), "=f"(b) : "l"(v));
}

// ============================================================================
// Projection kernel (R14, proven): 256 CTAs x 256 threads, 64 rows each.
// ============================================================================
#define PX_STRIDE 260
#define P_XS     0
#define P_WS0    (64*PX_STRIDE)
#define P_WS1    (P_WS0 + 16384)
#define P_STG    (P_WS1 + 16384)
#define PROJ_SMEM_BYTES ((P_STG + 4224)*4)

__device__ __forceinline__ void stage_fg(uint32_t wsb, const float* Wf,
                                         const float* Wg, int t) {
    #pragma unroll
    for (int s = 0; s < 16; s++) {
        int idx = t + 256*s;
        int k = idx >> 4, c4 = idx & 15;
        if (c4 < 8) cpa16(wsb + (uint32_t)(k*64 + c4*4)*4,        Wf + k*32 + c4*4);
        else        cpa16(wsb + (uint32_t)(k*64 + 32 + (c4-8)*4)*4, Wg + k*32 + (c4-8)*4);
    }
}
__device__ __forceinline__ void stage_wh(uint32_t wsb, const float* Whp, int t) {
    #pragma unroll
    for (int s = 0; s < 16; s++) {
        int idx = t + 256*s;
        int k = idx >> 4, c4 = idx & 15;
        cpa16(wsb + (uint32_t)(k*64 + c4*4)*4, Whp + k*NC + c4*4);
    }
}

__global__ __launch_bounds__(256) void proj_kernel(
    const float* __restrict__ x,
    const float* __restrict__ Wf, const float* __restrict__ bf,
    const float* __restrict__ Wg, const float* __restrict__ bg,
    const float* __restrict__ Wh, const float* __restrict__ bh)
{
    extern __shared__ float sm[];
    float* xs  = sm + P_XS;
    float* stg = sm + P_STG;
    const uint32_t smb = smem_u32(sm);
    const int t    = threadIdx.x;
    const int R0   = blockIdx.x * 64;
    const int bb   = R0 >> 12;
    const int key0 = R0 & (NN-1);

    {
        const float4* xg = (const float4*)(x + (size_t)R0*NC);
        #pragma unroll
        for (int s = 0; s < 16; s++) {
            int idx = t + 256*s;
            int row = idx >> 6, k4 = idx & 63;
            float4 v = xg[idx];
            float* dst = &xs[row*PX_STRIDE + k4*4];
            dst[0]=v.x; dst[1]=v.y; dst[2]=v.z; dst[3]=v.w;
        }
    }

    stage_fg(smb + P_WS0*4, Wf, Wg, t);
    cpa_commit();

    const int c0 = (t & 15) * 4;
    const int r0 = (t >> 4) * 4;

    for (int ph = 0; ph < 5; ph++) {
        cpa_wait<0>();
        __syncthreads();
        if (ph < 4) {
            stage_wh(smb + (((ph+1)&1) ? P_WS1 : P_WS0)*4, Wh + ph*64, t);
            cpa_commit();
        }
        const float* ws = sm + ((ph & 1) ? P_WS1 : P_WS0);

        unsigned long long accA[4], accB[4];
        #pragma unroll
        for (int a = 0; a < 4; a++) { accA[a] = 0ull; accB[a] = 0ull; }

        #pragma unroll 2
        for (int kk = 0; kk < 128; kk++) {
            int k = kk*2;
            float4 wv0 = *(const float4*)&ws[k*64 + c0];
            float4 wv1 = *(const float4*)&ws[(k+1)*64 + c0];
            unsigned long long wA0 = pk2(wv0.x, wv0.y), wB0 = pk2(wv0.z, wv0.w);
            unsigned long long wA1 = pk2(wv1.x, wv1.y), wB1 = pk2(wv1.z, wv1.w);
            #pragma unroll
            for (int rr = 0; rr < 4; rr++) {
                float2 xv = *(const float2*)&xs[(r0+rr)*PX_STRIDE + k];
                unsigned long long xb0 = pk2(xv.x, xv.x);
                unsigned long long xb1 = pk2(xv.y, xv.y);
                fma2(accA[rr], xb0, wA0);
                fma2(accB[rr], xb0, wB0);
                fma2(accA[rr], xb1, wA1);
                fma2(accB[rr], xb1, wB1);
            }
        }

        if (ph == 0) {
            float* sfhi = stg;                // [64 keys][33]
            #pragma unroll
            for (int rr = 0; rr < 4; rr++) {
                int lrow = r0 + rr;
                int grow = R0 + lrow;
                float v[4];
                unpk2(accA[rr], v[0], v[1]);
                unpk2(accB[rr], v[2], v[3]);
                if (c0 < 32) {
                    #pragma unroll
                    for (int q = 0; q < 4; q++)
                        sfhi[lrow*33 + c0 + q] = v[q] + bf[c0 + q];
                } else {
                    float w0 = v[0] + bg[c0-32], w1 = v[1] + bg[c0-31];
                    float w2 = v[2] + bg[c0-30], w3 = v[3] + bg[c0-29];
                    uint32_t h0 = packbf(w0, w1);
                    uint32_t l0 = packbf(w0 - bf_lo(h0), w1 - bf_hi(h0));
                    uint32_t h1 = packbf(w2, w3);
                    uint32_t l1 = packbf(w2 - bf_lo(h1), w3 - bf_hi(h1));
                    int cu = (c0 - 32) >> 1;
                    d_gbh[(size_t)grow*16 + cu    ] = h0;
                    d_gbl[(size_t)grow*16 + cu    ] = l0;
                    d_gbh[(size_t)grow*16 + cu + 1] = h1;
                    d_gbl[(size_t)grow*16 + cu + 1] = l1;
                }
            }
            __syncthreads();
            #pragma unroll
            for (int j = 0; j < 2; j++) {
                int idx = t + 256*j;
                int key = idx >> 3, e = idx & 7;
                int ks = e >> 2, tq2 = e & 3;
                int cb = 16*ks + 2*tq2;
                const float* fr = sfhi + key*33;
                float v0 = fr[cb], v1 = fr[cb+1], v8 = fr[cb+8], v9 = fr[cb+9];
                uint32_t hx = packbf(v0, v1);
                uint32_t hy = packbf(v8, v9);
                uint32_t lx = packbf(v0 - bf_lo(hx), v1 - bf_hi(hx));
                uint32_t ly = packbf(v8 - bf_lo(hy), v9 - bf_hi(hy));
                size_t dst = ((size_t)(bb*NN) + key0 + key)*8 + e;
                d_fqh[dst] = make_uint2(hx, hy);
                d_fql[dst] = make_uint2(lx, ly);
            }
        } else {
            float* sh = stg;                  // [64 keys][65] fp32
            #pragma unroll
            for (int rr = 0; rr < 4; rr++) {
                int lrow = r0 + rr;
                float v[4];
                unpk2(accA[rr], v[0], v[1]);
                unpk2(accB[rr], v[2], v[3]);
                #pragma unroll
                for (int q = 0; q < 4; q++) {
                    int c = c0 + q;
                    sh[lrow*65 + c] = v[q] + bh[(ph-1)*64 + c];
                }
            }
            __syncthreads();
            #pragma unroll
            for (int j = 0; j < 2; j++) {
                int idx = t + 256*j;
                int K16loc = idx >> 7;
                int tqv    = (idx >> 5) & 3;
                int qv     = idx & 31;
                int k2 = K16loc*16 + 2*tqv;
                uint4 u;
                u.x = packf16(sh[k2*65+qv],        sh[(k2+1)*65+qv]);
                u.y = packf16(sh[(k2+8)*65+qv],    sh[(k2+9)*65+qv]);
                u.z = packf16(sh[k2*65+qv+32],     sh[(k2+1)*65+qv+32]);
                u.w = packf16(sh[(k2+8)*65+qv+32], sh[(k2+9)*65+qv+32]);
                size_t dst = ((size_t)(bb*256 + (key0>>4) + K16loc)*4 + tqv)*128
                           + (ph-1)*32 + qv;
                d_hf4[dst] = u;
            }
        }
    }
}

// ============================================================================
// Flash attention: R16 math, TRIPLE-buffered f/h/P/scale, ONE global sync
// per tile. fp16 PV + online row-max, QK/PV pipelined. Grid (32,4), 512 thr.
// ============================================================================
#define FB_BYTES   6144
#define OFF_H_B    (6*FB_BYTES)              // 36864 (3 bufs x hi/lo)
#define H_STQ      130
#define H_TILE_B   (16*H_STQ*16)             // 33280
#define OFF_P_B    (OFF_H_B + 3*H_TILE_B)    // 136704
#define P_STRIDE   36
#define P_BUF_B    (128*P_STRIDE*4)          // 18432
#define OFF_SC_B   (OFF_P_B + 3*P_BUF_B)     // 192000
#define OFF_MX_B   (OFF_SC_B + 3*512)        // 193536
#define OFF_PS_B   (OFF_MX_B + 1024)         // 194560
#define ATT_SMEM_BYTES (OFF_PS_B + 1024 + 256)

__device__ __forceinline__ void attn_load_f(uint32_t smb, int bb, int kb, int buf, int t) {
    int arr = t >> 8, rem = t & 255;
    int key = rem >> 2, ep = rem & 3;
    const uint2* src = (arr ? d_fql : d_fqh)
                     + ((size_t)(bb*NN + kb*64 + key))*8 + ep*2;
    cpa16(smb + (uint32_t)((buf*2+arr)*FB_BYTES + key*96 + ep*16), src);
}
__device__ __forceinline__ void attn_load_h(uint32_t smb, int bb, int kb, int buf, int t) {
    #pragma unroll
    for (int s = 0; s < 4; s++) {
        int idx = t + 512*s;
        int K16loc = idx >> 9, rem = idx & 511;
        int tqv = rem >> 7, q = rem & 127;
        const uint4* src = d_hf4 + ((size_t)(bb*256 + kb*4 + K16loc)*4 + tqv)*128 + q;
        cpa16(smb + (uint32_t)(OFF_H_B + buf*H_TILE_B + ((K16loc*4+tqv)*H_STQ + q)*16), src);
    }
}

__global__ __launch_bounds__(512, 1) void attn_kernel(
    const float* __restrict__ x, float* __restrict__ out)
{
    extern __shared__ char smraw[];
    const uint32_t smb = smem_u32(smraw);
    const int t    = threadIdx.x;
    const int w    = t >> 5, lane = t & 31;
    const int g    = lane >> 2, tq = lane & 3;
    const int bb   = blockIdx.y;
    const int q0   = blockIdx.x * BM;
    const float L2E = 1.4426950408889634f;

    const int qg = w >> 1, kg = w & 1;
    const int mg = w >> 2, ng = w & 3;

    float* scbuf = (float*)(smraw + OFF_SC_B);   // [3][128]
    float* smax  = (float*)(smraw + OFF_MX_B);
    float* psum  = (float*)(smraw + OFF_PS_B);

    uint32_t ahi[2][4], alo[2][4];
    {
        const uint32_t* gbh = d_gbh + ((size_t)(bb*NN + q0 + qg*16))*16;
        const uint32_t* gbl = d_gbl + ((size_t)(bb*NN + q0 + qg*16))*16;
        #pragma unroll
        for (int ks = 0; ks < 2; ks++) {
            int cc = 8*ks + tq;
            ahi[ks][0] = gbh[g*16 + cc];
            ahi[ks][1] = gbh[(g+8)*16 + cc];
            ahi[ks][2] = gbh[g*16 + cc + 4];
            ahi[ks][3] = gbh[(g+8)*16 + cc + 4];
            alo[ks][0] = gbl[g*16 + cc];
            alo[ks][1] = gbl[(g+8)*16 + cc];
            alo[ks][2] = gbl[g*16 + cc + 4];
            alo[ks][3] = gbl[(g+8)*16 + cc + 4];
        }
    }

    float oacc[2][8][4];
    #pragma unroll
    for (int a=0;a<2;a++)
        #pragma unroll
        for (int b2=0;b2<8;b2++)
            #pragma unroll
            for (int c=0;c<4;c++) oacc[a][b2][c]=0.f;

    const float NEGINF = __int_as_float(0xff800000);
    float mold0 = NEGINF, mold1 = NEGINF;
    float ls0 = 0.f, ls1 = 0.f;
    const int row0 = qg*16 + g;

    attn_load_f(smb, bb, 0, 0, t);
    cpa_commit();

    int pb = 0;
    #pragma unroll 1
    for (int kb = 0; kb < NT; kb++) {
        const int pnext = (pb == 2) ? 0 : pb + 1;
        const int pprev = (pb == 0) ? 2 : pb - 1;
        // Prefetch into pnext: its last readers (QK(kb-2), f side) finished
        // before sync_top(kb-1). h(kb)->pb: last reader PV(kb-3) finished
        // before sync_top(kb-1). Single top barrier orders everything.
        if (kb + 1 < NT) attn_load_f(smb, bb, kb+1, pnext, t);
        cpa_commit();
        attn_load_h(smb, bb, kb, pb, t);
        cpa_commit();
        cpa_wait<2>();
        __syncthreads();                        // sync_top: the ONLY global sync

        // ---- QK(kb) from f[pb] ----
        const uint2* fbh = (const uint2*)(smraw + (pb*2+0)*FB_BYTES);
        const uint2* fbl = (const uint2*)(smraw + (pb*2+1)*FB_BYTES);
        float sacc[4][4];
        #pragma unroll
        for (int nt=0;nt<4;nt++)
            #pragma unroll
            for (int c=0;c<4;c++) sacc[nt][c]=0.f;

        #pragma unroll
        for (int ks = 0; ks < 2; ks++) {
            #pragma unroll
            for (int nt = 0; nt < 4; nt++) {
                int key = kg*32 + nt*8 + g;
                uint2 qh = fbh[key*12 + ks*4 + tq];
                uint2 ql = fbl[key*12 + ks*4 + tq];
                mma16(sacc[nt], ahi[ks], ql.x, ql.y);
                mma16(sacc[nt], alo[ks], qh.x, qh.y);
                mma16(sacc[nt], ahi[ks], qh.x, qh.y);
            }
        }

        // ---- online row max ----
        float m0 = fmaxf(fmaxf(sacc[0][0], sacc[0][1]), fmaxf(sacc[1][0], sacc[1][1]));
        m0 = fmaxf(m0, fmaxf(fmaxf(sacc[2][0], sacc[2][1]), fmaxf(sacc[3][0], sacc[3][1])));
        float m1 = fmaxf(fmaxf(sacc[0][2], sacc[0][3]), fmaxf(sacc[1][2], sacc[1][3]));
        m1 = fmaxf(m1, fmaxf(fmaxf(sacc[2][2], sacc[2][3]), fmaxf(sacc[3][2], sacc[3][3])));
        m0 = fmaxf(m0, __shfl_xor_sync(0xffffffffu, m0, 1));
        m0 = fmaxf(m0, __shfl_xor_sync(0xffffffffu, m0, 2));
        m1 = fmaxf(m1, __shfl_xor_sync(0xffffffffu, m1, 1));
        m1 = fmaxf(m1, __shfl_xor_sync(0xffffffffu, m1, 2));
        if (tq == 0) {
            smax[kg*128 + row0    ] = m0;
            smax[kg*128 + row0 + 8] = m1;
        }
        barx(1 + qg, 64);
        float mnew0 = fmaxf(mold0, fmaxf(smax[row0    ], smax[128 + row0    ]));
        float mnew1 = fmaxf(mold1, fmaxf(smax[row0 + 8], smax[128 + row0 + 8]));
        float sc0 = ex2((mold0 - mnew0) * L2E);
        float sc1 = ex2((mold1 - mnew1) * L2E);
        mold0 = mnew0; mold1 = mnew1;
        float m2n0 = mnew0 * L2E, m2n1 = mnew1 * L2E;
        if (kg == 0 && tq == 0) {
            scbuf[pb*128 + row0    ] = sc0;
            scbuf[pb*128 + row0 + 8] = sc1;
        }

        // ---- p = ex2(s*L2E - m2), fp16 pack, P[pb] store, reg row-sums ----
        {
            uint32_t* P = (uint32_t*)(smraw + OFF_P_B + pb*P_BUF_B);
            float rs0 = 0.f, rs1 = 0.f;
            #pragma unroll
            for (int nt = 0; nt < 4; nt++) {
                float p0 = ex2(fmaf(sacc[nt][0], L2E, -m2n0));
                float p1 = ex2(fmaf(sacc[nt][1], L2E, -m2n0));
                float p2 = ex2(fmaf(sacc[nt][2], L2E, -m2n1));
                float p3 = ex2(fmaf(sacc[nt][3], L2E, -m2n1));
                uint32_t u0 = packf16(p0, p1);
                uint32_t u1 = packf16(p2, p3);
                float2 f0 = __half22float2(*(const __half2*)&u0);
                float2 f1 = __half22float2(*(const __half2*)&u1);
                rs0 += f0.x + f0.y;
                rs1 += f1.x + f1.y;
                int cp = kg*16 + nt*4 + tq;
                P[(row0    )*P_STRIDE + cp] = u0;
                P[(row0 + 8)*P_STRIDE + cp] = u1;
            }
            rs0 += __shfl_xor_sync(0xffffffffu, rs0, 1);
            rs0 += __shfl_xor_sync(0xffffffffu, rs0, 2);
            rs1 += __shfl_xor_sync(0xffffffffu, rs1, 1);
            rs1 += __shfl_xor_sync(0xffffffffu, rs1, 2);
            ls0 = ls0*sc0 + rs0;
            ls1 = ls1*sc1 + rs1;
        }

        // ---- PV(kb-1) from P[pprev], h[pprev], scale[pprev] ----
        if (kb > 0) {
            const uint32_t* Pp = (const uint32_t*)(smraw + OFF_P_B + pprev*P_BUF_B);
            const uint4*    hq = (const uint4*)(smraw + OFF_H_B + pprev*H_TILE_B);
            const float*   scb = scbuf + pprev*128;
            float sc[2][2];
            #pragma unroll
            for (int mt = 0; mt < 2; mt++) {
                sc[mt][0] = scb[mg*32 + mt*16 + g    ];
                sc[mt][1] = scb[mg*32 + mt*16 + g + 8];
            }
            #pragma unroll
            for (int mt = 0; mt < 2; mt++)
                #pragma unroll
                for (int nt = 0; nt < 8; nt++) {
                    oacc[mt][nt][0] *= sc[mt][0];
                    oacc[mt][nt][1] *= sc[mt][0];
                    oacc[mt][nt][2] *= sc[mt][1];
                    oacc[mt][nt][3] *= sc[mt][1];
                }
            #pragma unroll
            for (int ks = 0; ks < 4; ks++) {
                uint32_t pa[2][4];
                #pragma unroll
                for (int mt = 0; mt < 2; mt++) {
                    int r = mg*32 + mt*16;
                    pa[mt][0] = Pp[(r+g  )*P_STRIDE + ks*8 + tq    ];
                    pa[mt][1] = Pp[(r+g+8)*P_STRIDE + ks*8 + tq    ];
                    pa[mt][2] = Pp[(r+g  )*P_STRIDE + ks*8 + tq + 4];
                    pa[mt][3] = Pp[(r+g+8)*P_STRIDE + ks*8 + tq + 4];
                }
                int rowb = (ks*4 + tq)*H_STQ;
                #pragma unroll
                for (int ntl = 0; ntl < 4; ntl++) {
                    uint4 u = hq[rowb + ng*32 + ntl*8 + g];
                    mma16h(oacc[0][ntl],   pa[0], u.x, u.y);
                    mma16h(oacc[1][ntl],   pa[1], u.x, u.y);
                    mma16h(oacc[0][ntl+4], pa[0], u.z, u.w);
                    mma16h(oacc[1][ntl+4], pa[1], u.z, u.w);
                }
            }
        }

        pb = pnext;
    }

    // publish register row-sums
    if (tq == 0) {
        psum[kg*128 + row0    ] = ls0;
        psum[kg*128 + row0 + 8] = ls1;
    }
    cpa_wait<0>();
    __syncthreads();

    // ---- final PV(NT-1): buffer (NT-1)%3 = pb-1 ----
    {
        const int plast = (pb == 0) ? 2 : pb - 1;
        const uint32_t* Pp = (const uint32_t*)(smraw + OFF_P_B + plast*P_BUF_B);
        const uint4*    hq = (const uint4*)(smraw + OFF_H_B + plast*H_TILE_B);
        const float*   scb = scbuf + plast*128;
        float sc[2][2];
        #pragma unroll
        for (int mt = 0; mt < 2; mt++) {
            sc[mt][0] = scb[mg*32 + mt*16 + g    ];
            sc[mt][1] = scb[mg*32 + mt*16 + g + 8];
        }
        #pragma unroll
        for (int mt = 0; mt < 2; mt++)
            #pragma unroll
            for (int nt = 0; nt < 8; nt++) {
                oacc[mt][nt][0] *= sc[mt][0];
                oacc[mt][nt][1] *= sc[mt][0];
                oacc[mt][nt][2] *= sc[mt][1];
                oacc[mt][nt][3] *= sc[mt][1];
            }
        #pragma unroll
        for (int ks = 0; ks < 4; ks++) {
            uint32_t pa[2][4];
            #pragma unroll
            for (int mt = 0; mt < 2; mt++) {
                int r = mg*32 + mt*16;
                pa[mt][0] = Pp[(r+g  )*P_STRIDE + ks*8 + tq    ];
                pa[mt][1] = Pp[(r+g+8)*P_STRIDE + ks*8 + tq    ];
                pa[mt][2] = Pp[(r+g  )*P_STRIDE + ks*8 + tq + 4];
                pa[mt][3] = Pp[(r+g+8)*P_STRIDE + ks*8 + tq + 4];
            }
            int rowb = (ks*4 + tq)*H_STQ;
            #pragma unroll
            for (int ntl = 0; ntl < 4; ntl++) {
                uint4 u = hq[rowb + ng*32 + ntl*8 + g];
                mma16h(oacc[0][ntl],   pa[0], u.x, u.y);
                mma16h(oacc[1][ntl],   pa[1], u.x, u.y);
                mma16h(oacc[0][ntl+4], pa[0], u.z, u.w);
                mma16h(oacc[1][ntl+4], pa[1], u.z, u.w);
            }
        }
    }

    // ---- epilogue: out = x + O / l ----
    #pragma unroll
    for (int mt = 0; mt < 2; mt++) {
        int r0 = mg*32 + mt*16 + g;
        float inv0 = 1.0f / (psum[r0    ] + psum[128 + r0    ]);
        float inv1 = 1.0f / (psum[r0 + 8] + psum[128 + r0 + 8]);
        #pragma unroll
        for (int nt = 0; nt < 8; nt++) {
            int col = ng*64 + nt*8 + 2*tq;
            size_t base0 = ((size_t)(bb*NN + q0 + r0))*NC + col;
            size_t base1 = base0 + (size_t)8*NC;
            float2 xv0 = *(const float2*)(x + base0);
            float2 xv1 = *(const float2*)(x + base1);
            float2 o0, o1;
            o0.x = xv0.x + oacc[mt][nt][0]*inv0;
            o0.y = xv0.y + oacc[mt][nt][1]*inv0;
            o1.x = xv1.x + oacc[mt][nt][2]*inv1;
            o1.y = xv1.y + oacc[mt][nt][3]*inv1;
            *(float2*)(out + base0) = o0;
            *(float2*)(out + base1) = o1;
        }
    }
}

extern "C" void kernel_launch(void* const* d_in, const int* in_sizes, int n_in,
                              void* d_out, int out_size) {
    (void)in_sizes; (void)n_in; (void)out_size;
    const float* x  = (const float*)d_in[0];
    const float* Wf = (const float*)d_in[1];
    const float* bf = (const float*)d_in[2];
    const float* Wg = (const float*)d_in[3];
    const float* bg = (const float*)d_in[4];
    const float* Wh = (const float*)d_in[5];
    const float* bh = (const float*)d_in[6];
    float* out = (float*)d_out;

    cudaFuncSetAttribute(proj_kernel, cudaFuncAttributeMaxDynamicSharedMemorySize,
                         PROJ_SMEM_BYTES);
    cudaFuncSetAttribute(attn_kernel, cudaFuncAttributeMaxDynamicSharedMemorySize,
                         ATT_SMEM_BYTES);

    proj_kernel<<<(NB*NN)/64, 256, PROJ_SMEM_BYTES>>>(x, Wf, bf, Wg, bg, Wh, bh);

    dim3 grid(NN/BM, NB);
    attn_kernel<<<grid, 512, ATT_SMEM_BYTES>>>(x, out);
}